// round 4
// baseline (speedup 1.0000x reference)
#include <cuda_runtime.h>
#include <math.h>

#define N 256
#define NTILE 128
#define BATCH 32

// 64 MB scratch: psi, rows y-major; x dimension stored in permuted spectral order
__device__ float2 g_psi[NTILE * N * N];
// permuted + prescaled transfer function: g_Hp[sx*256 + k2*32 + l] = H[k2+8*br5(l)][kx(sx)]/256
__device__ float2 g_Hp[N * N];
// per-lane twiddle table, SoA: comp c at g_twt[c*32 + l]
//   c 0..4   : Wf[s]  forward DIF stage twiddle (identity on bit-clear lanes)
//   c 5..9   : A[s]   inverse stage coeff on own value
//   c 10..14 : B[s]   inverse stage coeff on partner value
//   c 15..21 : wp[k]  W_256^{l*(k+1)}
__device__ float2 g_twt[22 * 32];

__device__ __forceinline__ float2 cmul(float2 a, float2 b) {
    return make_float2(fmaf(a.x, b.x, -a.y * b.y), fmaf(a.x, b.y, a.y * b.x));
}
// a * conj(b)
__device__ __forceinline__ float2 cmulc(float2 a, float2 b) {
    return make_float2(fmaf(a.x, b.x, a.y * b.y), fmaf(a.y, b.x, -a.x * b.y));
}
// A*v + B*p (complex)
__device__ __forceinline__ float2 cmul2(float2 A, float2 v, float2 B, float2 p) {
    float rx = fmaf(A.x, v.x, fmaf(-A.y, v.y, fmaf(B.x, p.x, -B.y * p.y)));
    float ry = fmaf(A.x, v.y, fmaf( A.y, v.x, fmaf(B.x, p.y,  B.y * p.x)));
    return make_float2(rx, ry);
}
__device__ __forceinline__ int br5(int x){ return (int)(__brev((unsigned)x) >> 27); }

// ---- packed f32x2 helpers (sm_100+) --------------------------------------
__device__ __forceinline__ float2 padd(float2 a, float2 b) {
    float2 r;
    asm("{\n\t.reg .b64 ua, ub, ur;\n\t"
        "mov.b64 ua, {%2,%3};\n\t"
        "mov.b64 ub, {%4,%5};\n\t"
        "add.rn.f32x2 ur, ua, ub;\n\t"
        "mov.b64 {%0,%1}, ur;\n\t}"
        : "=f"(r.x), "=f"(r.y)
        : "f"(a.x), "f"(a.y), "f"(b.x), "f"(b.y));
    return r;
}
// a*b + c, packed per component
__device__ __forceinline__ float2 pfma(float2 a, float2 b, float2 c) {
    float2 r;
    asm("{\n\t.reg .b64 ua, ub, uc, ur;\n\t"
        "mov.b64 ua, {%2,%3};\n\t"
        "mov.b64 ub, {%4,%5};\n\t"
        "mov.b64 uc, {%6,%7};\n\t"
        "fma.rn.f32x2 ur, ua, ub, uc;\n\t"
        "mov.b64 {%0,%1}, ur;\n\t}"
        : "=f"(r.x), "=f"(r.y)
        : "f"(a.x), "f"(a.y), "f"(b.x), "f"(b.y), "f"(c.x), "f"(c.y));
    return r;
}
__device__ __forceinline__ float2 psub(float2 a, float2 b) {
    return pfma(b, make_float2(-1.f, -1.f), a);   // a - b (exact)
}

// ---------------------------------------------------------------------------
// 8-point FFT in registers, natural in / natural out
template<bool INV>
__device__ __forceinline__ void fft8(float2 v[8]) {
    float2 a0=v[0], a1=v[4], a2=v[2], a3=v[6], a4=v[1], a5=v[5], a6=v[3], a7=v[7];
    float2 b0=padd(a0,a1), b1=psub(a0,a1);
    float2 b2=padd(a2,a3), b3=psub(a2,a3);
    float2 b4=padd(a4,a5), b5=psub(a4,a5);
    float2 b6=padd(a6,a7), b7=psub(a6,a7);
    float2 b3t = INV ? make_float2(-b3.y, b3.x) : make_float2(b3.y, -b3.x);
    float2 b7t = INV ? make_float2(-b7.y, b7.x) : make_float2(b7.y, -b7.x);
    float2 c0=padd(b0,b2), c2=psub(b0,b2);
    float2 c1=padd(b1,b3t), c3=psub(b1,b3t);
    float2 c4=padd(b4,b6), c6=psub(b4,b6);
    float2 c5=padd(b5,b7t), c7=psub(b5,b7t);
    const float r = 0.70710678118654752440f;
    float2 w1 = INV ? make_float2(r,  r) : make_float2( r, -r);
    float2 w3 = INV ? make_float2(-r, r) : make_float2(-r, -r);
    float2 c5t = cmul(c5, w1);
    float2 c6t = INV ? make_float2(-c6.y, c6.x) : make_float2(c6.y, -c6.x);
    float2 c7t = cmul(c7, w3);
    v[0]=padd(c0,c4); v[4]=psub(c0,c4);
    v[1]=padd(c1,c5t); v[5]=psub(c1,c5t);
    v[2]=padd(c2,c6t); v[6]=psub(c2,c6t);
    v[3]=padd(c3,c7t); v[7]=psub(c3,c7t);
}

// 32-pt FFT across lanes, forward DIF: natural in -> bit-reversed lanes out
__device__ __forceinline__ void lane_fwd(float2 v[8], const float2* tt, int l) {
    #pragma unroll
    for (int s = 0; s < 5; s++) {
        const int h = 16 >> s;
        const float sgn = (l & h) ? -1.f : 1.f;
        const float2 sgnP = make_float2(sgn, sgn);
        const float2 W = tt[s * 32];
        #pragma unroll
        for (int k = 0; k < 8; k++) {
            float px = __shfl_xor_sync(0xffffffffu, v[k].x, h);
            float py = __shfl_xor_sync(0xffffffffu, v[k].y, h);
            float2 u = pfma(v[k], sgnP, make_float2(px, py));
            v[k] = cmul(u, W);
        }
    }
}
// inverse DIT: bit-reversed lanes in -> natural out; out = A*v + B*p
__device__ __forceinline__ void lane_inv(float2 v[8], const float2* tt, int l) {
    #pragma unroll
    for (int s = 0; s < 5; s++) {
        const int h = 1 << s;
        const float2 A = tt[(5 + s) * 32];
        const float2 B = tt[(10 + s) * 32];
        #pragma unroll
        for (int k = 0; k < 8; k++) {
            float px = __shfl_xor_sync(0xffffffffu, v[k].x, h);
            float py = __shfl_xor_sync(0xffffffffu, v[k].y, h);
            v[k] = cmul2(A, v[k], B, make_float2(px, py));
        }
    }
}

// Full 256-pt line FFT. Input v[n2] = x[l + 32*n2];
// output v[k2] = X[k2 + 8*br5(l)] (stored at k2*32+l -> permuted spectral)
__device__ __forceinline__ void fwd256(float2 v[8], const float2* tt, int l) {
    fft8<false>(v);
    #pragma unroll
    for (int k = 1; k < 8; k++) v[k] = cmul(v[k], tt[(15 + k - 1) * 32]);
    lane_fwd(v, tt, l);
}
// exact unnormalized inverse of fwd256 (x256)
__device__ __forceinline__ void inv256(float2 v[8], const float2* tt, int l) {
    lane_inv(v, tt, l);
    #pragma unroll
    for (int k = 1; k < 8; k++) v[k] = cmulc(v[k], tt[(15 + k - 1) * 32]);
    fft8<true>(v);
}

// ---------------------------------------------------------------------------
// Build permuted/prescaled H table and the per-lane twiddle table
__global__ void k_prep(const float* __restrict__ Hr, const float* __restrict__ Hi) {
    int o = blockIdx.x * 256 + threadIdx.x;       // 65536 total
    int s = o >> 8, j = o & 255;
    int ky = (j >> 5) + 8 * br5(j & 31);
    int kx = (s >> 5) + 8 * br5(s & 31);
    int src = ky * N + kx;
    g_Hp[o] = make_float2(Hr[src] * (1.f/256.f), Hi[src] * (1.f/256.f));

    if (o < 32) {
        const int l = o;
        // forward stage twiddles (h = 16 >> s)
        for (int st = 0; st < 5; st++) {
            const int h = 16 >> st;
            const int idx = l & (h - 1);
            float sn, cs;
            sincospif((float)idx / (float)h, &sn, &cs);   // W = (cs,-sn)
            g_twt[st * 32 + l] = (l & h) ? make_float2(cs, -sn) : make_float2(1.f, 0.f);
        }
        // inverse stage coeffs (h = 1 << s): conjW = (cs, sn)
        for (int st = 0; st < 5; st++) {
            const int h = 1 << st;
            const int idx = l & (h - 1);
            float sn, cs;
            sincospif((float)idx / (float)h, &sn, &cs);
            float2 A = (l & h) ? make_float2(-cs, -sn) : make_float2(1.f, 0.f);
            float2 B = (l & h) ? make_float2(1.f, 0.f) : make_float2(cs, sn);
            g_twt[(5 + st) * 32 + l]  = A;
            g_twt[(10 + st) * 32 + l] = B;
        }
        // W_256^{l*k}, k=1..7
        float sn, cs;
        sincospif((float)l / 128.f, &sn, &cs);
        float2 w1 = make_float2(cs, -sn);
        float2 wk = w1;
        g_twt[15 * 32 + l] = wk;
        for (int k = 2; k <= 7; k++) {
            wk = cmul(wk, w1);
            g_twt[(15 + k - 1) * 32 + l] = wk;
        }
    }
}

// ---------------------------------------------------------------------------
// Init: psi0 = bilinear(probe) * obj[0], forward row FFT -> g_psi (no smem)
__global__ void __launch_bounds__(256) k_init_row(
        const float* __restrict__ obj, const float* __restrict__ probe,
        const float* __restrict__ shifts, const int* __restrict__ cpos,
        const int* __restrict__ idxs) {
    const int t = threadIdx.x, l = t & 31, w = t >> 5;
    const float2* tt = g_twt + l;

    const int tile = blockIdx.y;
    const int b = tile >> 2, m = tile & 3;
    const int y = blockIdx.x * 8 + w;
    const int idx = idxs[b];
    const int py = cpos[2*idx], px = cpos[2*idx + 1];
    const float tH = shifts[2*idx], tW = shifts[2*idx + 1];
    const float oyf = floorf(-tH), oxf = floorf(-tW);
    const int oy = (int)oyf, ox = (int)oxf;
    const float wy = -tH - oyf, wx = -tW - oxf;
    const float w00 = (1.f-wy)*(1.f-wx), w01 = (1.f-wy)*wx;
    const float w10 = wy*(1.f-wx),       w11 = wy*wx;

    const int yy0 = y + oy;
    const bool v0 = (yy0 >= 0) && (yy0 < N);
    const bool v1 = (yy0 + 1 >= 0) && (yy0 + 1 < N);
    const float2* pr = (const float2*)probe + m * N * N;
    const float2* ob = (const float2*)obj + (py + y) * 1024 + px;   // slice 0

    float2 v[8];
    #pragma unroll
    for (int n2 = 0; n2 < 8; n2++) {
        const int x = l + 32 * n2;
        const int xx0 = x + ox;
        const bool u0 = (xx0 >= 0) && (xx0 < N);
        const bool u1 = (xx0 + 1 >= 0) && (xx0 + 1 < N);
        float2 z = make_float2(0.f, 0.f);
        float2 p00 = (v0 && u0) ? pr[yy0*N + xx0]       : z;
        float2 p01 = (v0 && u1) ? pr[yy0*N + xx0 + 1]   : z;
        float2 p10 = (v1 && u0) ? pr[(yy0+1)*N + xx0]   : z;
        float2 p11 = (v1 && u1) ? pr[(yy0+1)*N + xx0+1] : z;
        float amp = w00*p00.x + w01*p01.x + w10*p10.x + w11*p11.x;
        float ph  = w00*p00.y + w01*p01.y + w10*p10.y + w11*p11.y;
        float s, c; __sincosf(ph, &s, &c);
        float2 pc = make_float2(amp * c, amp * s);
        float2 o = ob[x];
        float s2, c2; __sincosf(o.y, &s2, &c2);
        v[n2] = cmul(pc, make_float2(o.x * c2, o.x * s2));
    }
    fwd256(v, tt, l);
    float2* gp = g_psi + tile * N * N + y * N;
    #pragma unroll
    for (int k2 = 0; k2 < 8; k2++) gp[k2*32 + l] = v[k2];
}

// ---------------------------------------------------------------------------
// Column pass: Fy -> *H/256 -> IFy per storage-column. smem only for staging.
__global__ void __launch_bounds__(256) k_col() {
    __shared__ float2 sm[8 * 257];
    const int t = threadIdx.x, l = t & 31, w = t >> 5;
    const float2* tt = g_twt + l;

    const int tile = blockIdx.y;
    const int sx0 = blockIdx.x * 8;
    float2* gp = g_psi + tile * N * N;

    #pragma unroll
    for (int k = 0; k < 8; k++) {
        const int e = t + k * 256;
        const int y = e >> 3, c = e & 7;
        sm[c * 257 + y] = gp[y * N + sx0 + c];
    }
    __syncthreads();

    float2 v[8];
    #pragma unroll
    for (int n2 = 0; n2 < 8; n2++) v[n2] = sm[w * 257 + l + 32 * n2];
    fwd256(v, tt, l);
    const float2* hp = g_Hp + (sx0 + w) * N;
    #pragma unroll
    for (int k2 = 0; k2 < 8; k2++) v[k2] = cmul(v[k2], hp[k2*32 + l]);
    inv256(v, tt, l);
    #pragma unroll
    for (int n2 = 0; n2 < 8; n2++) sm[w * 257 + l + 32 * n2] = v[n2];
    __syncthreads();

    #pragma unroll
    for (int k = 0; k < 8; k++) {
        const int e = t + k * 256;
        const int y = e >> 3, c = e & 7;
        gp[y * N + sx0 + c] = sm[c * 257 + y];
    }
}

// ---------------------------------------------------------------------------
// Mid row pass: IFx -> *obj[z]/256 -> Fx. Fully register/shuffle, no smem.
__global__ void __launch_bounds__(256) k_mid_row(
        const float* __restrict__ obj, const int* __restrict__ cpos,
        const int* __restrict__ idxs, int z) {
    const int t = threadIdx.x, l = t & 31, w = t >> 5;
    const float2* tt = g_twt + l;

    const int tile = blockIdx.y, b = tile >> 2;
    const int y = blockIdx.x * 8 + w;
    const int idx = idxs[b];
    const int py = cpos[2*idx], px = cpos[2*idx + 1];

    float2* gp = g_psi + tile * N * N + y * N;
    float2 v[8];
    #pragma unroll
    for (int k2 = 0; k2 < 8; k2++) v[k2] = gp[k2*32 + l];
    inv256(v, tt, l);

    const float2* ob = (const float2*)obj + (size_t)z * 1024 * 1024 + (py + y) * 1024 + px;
    #pragma unroll
    for (int n2 = 0; n2 < 8; n2++) {
        float2 o = ob[l + 32 * n2];
        float s, c; __sincosf(o.y, &s, &c);
        const float a = o.x * (1.f / 256.f);
        v[n2] = cmul(v[n2], make_float2(a * c, a * s));
    }
    fwd256(v, tt, l);
    #pragma unroll
    for (int k2 = 0; k2 < 8; k2++) gp[k2*32 + l] = v[k2];
}

// ---------------------------------------------------------------------------
// Final: Fy per column, sum |.|^2 over 4 modes, scatter to true (ky,kx)
__global__ void __launch_bounds__(256) k_final(float* __restrict__ out) {
    __shared__ float2 sm[8 * 257];
    const int t = threadIdx.x, l = t & 31, w = t >> 5;
    const float2* tt = g_twt + l;

    const int b = blockIdx.y;
    const int sx0 = blockIdx.x * 8;
    float acc[8];
    #pragma unroll
    for (int k = 0; k < 8; k++) acc[k] = 0.f;

    for (int m = 0; m < 4; m++) {
        const float2* gp = g_psi + (size_t)(b * 4 + m) * N * N;
        __syncthreads();
        #pragma unroll
        for (int k = 0; k < 8; k++) {
            const int e = t + k * 256;
            sm[(e & 7) * 257 + (e >> 3)] = gp[(e >> 3) * N + sx0 + (e & 7)];
        }
        __syncthreads();
        float2 v[8];
        #pragma unroll
        for (int n2 = 0; n2 < 8; n2++) v[n2] = sm[w * 257 + l + 32 * n2];
        fwd256(v, tt, l);
        #pragma unroll
        for (int k2 = 0; k2 < 8; k2++)
            acc[k2] = fmaf(v[k2].x, v[k2].x, fmaf(v[k2].y, v[k2].y, acc[k2]));
    }
    const int s = sx0 + w;
    const int kx = (s >> 5) + 8 * br5(s & 31);
    const int kyb = 8 * br5(l);
    #pragma unroll
    for (int k2 = 0; k2 < 8; k2++)
        out[b * N * N + (k2 + kyb) * N + kx] = acc[k2];
}

// ---------------------------------------------------------------------------
extern "C" void kernel_launch(void* const* d_in, const int* in_sizes, int n_in,
                              void* d_out, int out_size) {
    const float* obj    = (const float*)d_in[0];
    const float* probe  = (const float*)d_in[1];
    const float* shifts = (const float*)d_in[2];
    const int*   cpos   = (const int*)d_in[3];
    const float* Hr     = (const float*)d_in[4];
    const float* Hi     = (const float*)d_in[5];
    const int*   idxs   = (const int*)d_in[6];
    float* out = (float*)d_out;

    k_prep<<<256, 256>>>(Hr, Hi);

    dim3 g(32, NTILE);
    k_init_row<<<g, 256>>>(obj, probe, shifts, cpos, idxs);
    for (int z = 0; z < 7; z++) {
        k_col<<<g, 256>>>();
        k_mid_row<<<g, 256>>>(obj, cpos, idxs, z + 1);
    }
    dim3 gf(32, BATCH);
    k_final<<<gf, 256>>>(out);
}

// round 5
// speedup vs baseline: 1.0004x; 1.0004x over previous
#include <cuda_runtime.h>
#include <math.h>

#define N 256
#define NTILE 128
#define BATCH 32

// 64 MB scratch: psi, rows y-major; x dimension stored in permuted spectral order
__device__ float2 g_psi[NTILE * N * N];
// permuted + prescaled transfer function: g_Hp[sx*256 + k2*32 + l] = H[k2+8*br5(l)][kx(sx)]/256
__device__ float2 g_Hp[N * N];
// per-lane twiddle table, SoA: comp c at g_twt[c*32 + l]
//   c 0..4   : Wf[s]  forward DIF stage twiddle (identity on bit-clear lanes)
//   c 5..9   : A[s]   inverse stage coeff on own value
//   c 10..14 : B[s]   inverse stage coeff on partner value
//   c 15..21 : wp[k]  W_256^{l*(k+1)}
__device__ float2 g_twt[22 * 32];

__device__ __forceinline__ float2 cmul(float2 a, float2 b) {
    return make_float2(fmaf(a.x, b.x, -a.y * b.y), fmaf(a.x, b.y, a.y * b.x));
}
// a * conj(b)
__device__ __forceinline__ float2 cmulc(float2 a, float2 b) {
    return make_float2(fmaf(a.x, b.x, a.y * b.y), fmaf(a.y, b.x, -a.x * b.y));
}
// A*v + B*p (complex)
__device__ __forceinline__ float2 cmul2(float2 A, float2 v, float2 B, float2 p) {
    float rx = fmaf(A.x, v.x, fmaf(-A.y, v.y, fmaf(B.x, p.x, -B.y * p.y)));
    float ry = fmaf(A.x, v.y, fmaf( A.y, v.x, fmaf(B.x, p.y,  B.y * p.x)));
    return make_float2(rx, ry);
}
__device__ __forceinline__ int br5(int x){ return (int)(__brev((unsigned)x) >> 27); }

// ---- packed f32x2 helpers (sm_100+) --------------------------------------
__device__ __forceinline__ float2 padd(float2 a, float2 b) {
    float2 r;
    asm("{\n\t.reg .b64 ua, ub, ur;\n\t"
        "mov.b64 ua, {%2,%3};\n\t"
        "mov.b64 ub, {%4,%5};\n\t"
        "add.rn.f32x2 ur, ua, ub;\n\t"
        "mov.b64 {%0,%1}, ur;\n\t}"
        : "=f"(r.x), "=f"(r.y)
        : "f"(a.x), "f"(a.y), "f"(b.x), "f"(b.y));
    return r;
}
// a*b + c, packed per component
__device__ __forceinline__ float2 pfma(float2 a, float2 b, float2 c) {
    float2 r;
    asm("{\n\t.reg .b64 ua, ub, uc, ur;\n\t"
        "mov.b64 ua, {%2,%3};\n\t"
        "mov.b64 ub, {%4,%5};\n\t"
        "mov.b64 uc, {%6,%7};\n\t"
        "fma.rn.f32x2 ur, ua, ub, uc;\n\t"
        "mov.b64 {%0,%1}, ur;\n\t}"
        : "=f"(r.x), "=f"(r.y)
        : "f"(a.x), "f"(a.y), "f"(b.x), "f"(b.y), "f"(c.x), "f"(c.y));
    return r;
}
__device__ __forceinline__ float2 psub(float2 a, float2 b) {
    return pfma(b, make_float2(-1.f, -1.f), a);   // a - b (exact)
}

// ---------------------------------------------------------------------------
// 8-point FFT in registers, natural in / natural out
template<bool INV>
__device__ __forceinline__ void fft8(float2 v[8]) {
    float2 a0=v[0], a1=v[4], a2=v[2], a3=v[6], a4=v[1], a5=v[5], a6=v[3], a7=v[7];
    float2 b0=padd(a0,a1), b1=psub(a0,a1);
    float2 b2=padd(a2,a3), b3=psub(a2,a3);
    float2 b4=padd(a4,a5), b5=psub(a4,a5);
    float2 b6=padd(a6,a7), b7=psub(a6,a7);
    float2 b3t = INV ? make_float2(-b3.y, b3.x) : make_float2(b3.y, -b3.x);
    float2 b7t = INV ? make_float2(-b7.y, b7.x) : make_float2(b7.y, -b7.x);
    float2 c0=padd(b0,b2), c2=psub(b0,b2);
    float2 c1=padd(b1,b3t), c3=psub(b1,b3t);
    float2 c4=padd(b4,b6), c6=psub(b4,b6);
    float2 c5=padd(b5,b7t), c7=psub(b5,b7t);
    const float r = 0.70710678118654752440f;
    float2 w1 = INV ? make_float2(r,  r) : make_float2( r, -r);
    float2 w3 = INV ? make_float2(-r, r) : make_float2(-r, -r);
    float2 c5t = cmul(c5, w1);
    float2 c6t = INV ? make_float2(-c6.y, c6.x) : make_float2(c6.y, -c6.x);
    float2 c7t = cmul(c7, w3);
    v[0]=padd(c0,c4); v[4]=psub(c0,c4);
    v[1]=padd(c1,c5t); v[5]=psub(c1,c5t);
    v[2]=padd(c2,c6t); v[6]=psub(c2,c6t);
    v[3]=padd(c3,c7t); v[7]=psub(c3,c7t);
}

// 32-pt FFT across lanes, forward DIF: natural in -> bit-reversed lanes out
__device__ __forceinline__ void lane_fwd(float2 v[8], const float2* tt, int l) {
    #pragma unroll
    for (int s = 0; s < 5; s++) {
        const int h = 16 >> s;
        const float sgn = (l & h) ? -1.f : 1.f;
        const float2 sgnP = make_float2(sgn, sgn);
        const float2 W = tt[s * 32];
        #pragma unroll
        for (int k = 0; k < 8; k++) {
            float px = __shfl_xor_sync(0xffffffffu, v[k].x, h);
            float py = __shfl_xor_sync(0xffffffffu, v[k].y, h);
            float2 u = pfma(v[k], sgnP, make_float2(px, py));
            v[k] = cmul(u, W);
        }
    }
}
// inverse DIT: bit-reversed lanes in -> natural out; out = A*v + B*p
__device__ __forceinline__ void lane_inv(float2 v[8], const float2* tt, int l) {
    #pragma unroll
    for (int s = 0; s < 5; s++) {
        const int h = 1 << s;
        const float2 A = tt[(5 + s) * 32];
        const float2 B = tt[(10 + s) * 32];
        #pragma unroll
        for (int k = 0; k < 8; k++) {
            float px = __shfl_xor_sync(0xffffffffu, v[k].x, h);
            float py = __shfl_xor_sync(0xffffffffu, v[k].y, h);
            v[k] = cmul2(A, v[k], B, make_float2(px, py));
        }
    }
}

// Full 256-pt line FFT. Input v[n2] = x[l + 32*n2];
// output v[k2] = X[k2 + 8*br5(l)] (stored at k2*32+l -> permuted spectral)
__device__ __forceinline__ void fwd256(float2 v[8], const float2* tt, int l) {
    fft8<false>(v);
    #pragma unroll
    for (int k = 1; k < 8; k++) v[k] = cmul(v[k], tt[(15 + k - 1) * 32]);
    lane_fwd(v, tt, l);
}
// exact unnormalized inverse of fwd256 (x256)
__device__ __forceinline__ void inv256(float2 v[8], const float2* tt, int l) {
    lane_inv(v, tt, l);
    #pragma unroll
    for (int k = 1; k < 8; k++) v[k] = cmulc(v[k], tt[(15 + k - 1) * 32]);
    fft8<true>(v);
}

// ---------------------------------------------------------------------------
// Build permuted/prescaled H table and the per-lane twiddle table
__global__ void k_prep(const float* __restrict__ Hr, const float* __restrict__ Hi) {
    int o = blockIdx.x * 256 + threadIdx.x;       // 65536 total
    int s = o >> 8, j = o & 255;
    int ky = (j >> 5) + 8 * br5(j & 31);
    int kx = (s >> 5) + 8 * br5(s & 31);
    int src = ky * N + kx;
    g_Hp[o] = make_float2(Hr[src] * (1.f/256.f), Hi[src] * (1.f/256.f));

    if (o < 32) {
        const int l = o;
        // forward stage twiddles (h = 16 >> s)
        for (int st = 0; st < 5; st++) {
            const int h = 16 >> st;
            const int idx = l & (h - 1);
            float sn, cs;
            sincospif((float)idx / (float)h, &sn, &cs);   // W = (cs,-sn)
            g_twt[st * 32 + l] = (l & h) ? make_float2(cs, -sn) : make_float2(1.f, 0.f);
        }
        // inverse stage coeffs (h = 1 << s): conjW = (cs, sn)
        for (int st = 0; st < 5; st++) {
            const int h = 1 << st;
            const int idx = l & (h - 1);
            float sn, cs;
            sincospif((float)idx / (float)h, &sn, &cs);
            float2 A = (l & h) ? make_float2(-cs, -sn) : make_float2(1.f, 0.f);
            float2 B = (l & h) ? make_float2(1.f, 0.f) : make_float2(cs, sn);
            g_twt[(5 + st) * 32 + l]  = A;
            g_twt[(10 + st) * 32 + l] = B;
        }
        // W_256^{l*k}, k=1..7
        float sn, cs;
        sincospif((float)l / 128.f, &sn, &cs);
        float2 w1 = make_float2(cs, -sn);
        float2 wk = w1;
        g_twt[15 * 32 + l] = wk;
        for (int k = 2; k <= 7; k++) {
            wk = cmul(wk, w1);
            g_twt[(15 + k - 1) * 32 + l] = wk;
        }
    }
}

// ---------------------------------------------------------------------------
// Init: psi0 = bilinear(probe) * obj[0], forward row FFT -> g_psi (no smem)
__global__ void __launch_bounds__(256) k_init_row(
        const float* __restrict__ obj, const float* __restrict__ probe,
        const float* __restrict__ shifts, const int* __restrict__ cpos,
        const int* __restrict__ idxs) {
    const int t = threadIdx.x, l = t & 31, w = t >> 5;
    const float2* tt = g_twt + l;

    const int tile = blockIdx.y;
    const int b = tile >> 2, m = tile & 3;
    const int y = blockIdx.x * 8 + w;
    const int idx = idxs[b];
    const int py = cpos[2*idx], px = cpos[2*idx + 1];
    const float tH = shifts[2*idx], tW = shifts[2*idx + 1];
    const float oyf = floorf(-tH), oxf = floorf(-tW);
    const int oy = (int)oyf, ox = (int)oxf;
    const float wy = -tH - oyf, wx = -tW - oxf;
    const float w00 = (1.f-wy)*(1.f-wx), w01 = (1.f-wy)*wx;
    const float w10 = wy*(1.f-wx),       w11 = wy*wx;

    const int yy0 = y + oy;
    const bool v0 = (yy0 >= 0) && (yy0 < N);
    const bool v1 = (yy0 + 1 >= 0) && (yy0 + 1 < N);
    const float2* pr = (const float2*)probe + m * N * N;
    const float2* ob = (const float2*)obj + (py + y) * 1024 + px;   // slice 0

    float2 v[8];
    #pragma unroll
    for (int n2 = 0; n2 < 8; n2++) {
        const int x = l + 32 * n2;
        const int xx0 = x + ox;
        const bool u0 = (xx0 >= 0) && (xx0 < N);
        const bool u1 = (xx0 + 1 >= 0) && (xx0 + 1 < N);
        float2 z = make_float2(0.f, 0.f);
        float2 p00 = (v0 && u0) ? pr[yy0*N + xx0]       : z;
        float2 p01 = (v0 && u1) ? pr[yy0*N + xx0 + 1]   : z;
        float2 p10 = (v1 && u0) ? pr[(yy0+1)*N + xx0]   : z;
        float2 p11 = (v1 && u1) ? pr[(yy0+1)*N + xx0+1] : z;
        float amp = w00*p00.x + w01*p01.x + w10*p10.x + w11*p11.x;
        float ph  = w00*p00.y + w01*p01.y + w10*p10.y + w11*p11.y;
        float s, c; __sincosf(ph, &s, &c);
        float2 pc = make_float2(amp * c, amp * s);
        float2 o = ob[x];
        float s2, c2; __sincosf(o.y, &s2, &c2);
        v[n2] = cmul(pc, make_float2(o.x * c2, o.x * s2));
    }
    fwd256(v, tt, l);
    float2* gp = g_psi + tile * N * N + y * N;
    #pragma unroll
    for (int k2 = 0; k2 < 8; k2++) gp[k2*32 + l] = v[k2];
}

// ---------------------------------------------------------------------------
// Column pass: Fy -> *H/256 -> IFy per storage-column. smem only for staging.
__global__ void __launch_bounds__(256) k_col() {
    __shared__ float2 sm[8 * 257];
    const int t = threadIdx.x, l = t & 31, w = t >> 5;
    const float2* tt = g_twt + l;

    const int tile = blockIdx.y;
    const int sx0 = blockIdx.x * 8;
    float2* gp = g_psi + tile * N * N;

    #pragma unroll
    for (int k = 0; k < 8; k++) {
        const int e = t + k * 256;
        const int y = e >> 3, c = e & 7;
        sm[c * 257 + y] = gp[y * N + sx0 + c];
    }
    __syncthreads();

    float2 v[8];
    #pragma unroll
    for (int n2 = 0; n2 < 8; n2++) v[n2] = sm[w * 257 + l + 32 * n2];
    fwd256(v, tt, l);
    const float2* hp = g_Hp + (sx0 + w) * N;
    #pragma unroll
    for (int k2 = 0; k2 < 8; k2++) v[k2] = cmul(v[k2], hp[k2*32 + l]);
    inv256(v, tt, l);
    #pragma unroll
    for (int n2 = 0; n2 < 8; n2++) sm[w * 257 + l + 32 * n2] = v[n2];
    __syncthreads();

    #pragma unroll
    for (int k = 0; k < 8; k++) {
        const int e = t + k * 256;
        const int y = e >> 3, c = e & 7;
        gp[y * N + sx0 + c] = sm[c * 257 + y];
    }
}

// ---------------------------------------------------------------------------
// Mid row pass: IFx -> *obj[z]/256 -> Fx. Fully register/shuffle, no smem.
__global__ void __launch_bounds__(256) k_mid_row(
        const float* __restrict__ obj, const int* __restrict__ cpos,
        const int* __restrict__ idxs, int z) {
    const int t = threadIdx.x, l = t & 31, w = t >> 5;
    const float2* tt = g_twt + l;

    const int tile = blockIdx.y, b = tile >> 2;
    const int y = blockIdx.x * 8 + w;
    const int idx = idxs[b];
    const int py = cpos[2*idx], px = cpos[2*idx + 1];

    float2* gp = g_psi + tile * N * N + y * N;
    float2 v[8];
    #pragma unroll
    for (int k2 = 0; k2 < 8; k2++) v[k2] = gp[k2*32 + l];
    inv256(v, tt, l);

    const float2* ob = (const float2*)obj + (size_t)z * 1024 * 1024 + (py + y) * 1024 + px;
    #pragma unroll
    for (int n2 = 0; n2 < 8; n2++) {
        float2 o = ob[l + 32 * n2];
        float s, c; __sincosf(o.y, &s, &c);
        const float a = o.x * (1.f / 256.f);
        v[n2] = cmul(v[n2], make_float2(a * c, a * s));
    }
    fwd256(v, tt, l);
    #pragma unroll
    for (int k2 = 0; k2 < 8; k2++) gp[k2*32 + l] = v[k2];
}

// ---------------------------------------------------------------------------
// Final: Fy per column, sum |.|^2 over 4 modes, scatter to true (ky,kx)
__global__ void __launch_bounds__(256) k_final(float* __restrict__ out) {
    __shared__ float2 sm[8 * 257];
    const int t = threadIdx.x, l = t & 31, w = t >> 5;
    const float2* tt = g_twt + l;

    const int b = blockIdx.y;
    const int sx0 = blockIdx.x * 8;
    float acc[8];
    #pragma unroll
    for (int k = 0; k < 8; k++) acc[k] = 0.f;

    for (int m = 0; m < 4; m++) {
        const float2* gp = g_psi + (size_t)(b * 4 + m) * N * N;
        __syncthreads();
        #pragma unroll
        for (int k = 0; k < 8; k++) {
            const int e = t + k * 256;
            sm[(e & 7) * 257 + (e >> 3)] = gp[(e >> 3) * N + sx0 + (e & 7)];
        }
        __syncthreads();
        float2 v[8];
        #pragma unroll
        for (int n2 = 0; n2 < 8; n2++) v[n2] = sm[w * 257 + l + 32 * n2];
        fwd256(v, tt, l);
        #pragma unroll
        for (int k2 = 0; k2 < 8; k2++)
            acc[k2] = fmaf(v[k2].x, v[k2].x, fmaf(v[k2].y, v[k2].y, acc[k2]));
    }
    const int s = sx0 + w;
    const int kx = (s >> 5) + 8 * br5(s & 31);
    const int kyb = 8 * br5(l);
    #pragma unroll
    for (int k2 = 0; k2 < 8; k2++)
        out[b * N * N + (k2 + kyb) * N + kx] = acc[k2];
}

// ---------------------------------------------------------------------------
extern "C" void kernel_launch(void* const* d_in, const int* in_sizes, int n_in,
                              void* d_out, int out_size) {
    const float* obj    = (const float*)d_in[0];
    const float* probe  = (const float*)d_in[1];
    const float* shifts = (const float*)d_in[2];
    const int*   cpos   = (const int*)d_in[3];
    const float* Hr     = (const float*)d_in[4];
    const float* Hi     = (const float*)d_in[5];
    const int*   idxs   = (const int*)d_in[6];
    float* out = (float*)d_out;

    k_prep<<<256, 256>>>(Hr, Hi);

    dim3 g(32, NTILE);
    k_init_row<<<g, 256>>>(obj, probe, shifts, cpos, idxs);
    for (int z = 0; z < 7; z++) {
        k_col<<<g, 256>>>();
        k_mid_row<<<g, 256>>>(obj, cpos, idxs, z + 1);
    }
    dim3 gf(32, BATCH);
    k_final<<<gf, 256>>>(out);
}